// round 1
// baseline (speedup 1.0000x reference)
#include <cuda_runtime.h>
#include <cstdio>

#define EMBD   300
#define EMB_P  304      // padded K for gemm1
#define EMB2   600
#define NLAY   5
#define NMAX   100000

// ---------------- static scratch (device globals; no runtime allocs) ----------------
__device__ float g_h  [(size_t)NMAX * EMBD];    // h between layers
__device__ float g_z  [(size_t)NMAX * EMB_P];   // z = (1+eps)h + agg, padded
__device__ float g_t1 [(size_t)NMAX * EMB2];    // gemm1 output
__device__ float g_z2 [(size_t)NMAX * EMBD];    // gemm2 output
__device__ float g_W1p[NLAY * EMB2 * EMB_P];    // W1 padded to K=304
__device__ float g_etab[NLAY * 9 * EMBD];       // 9 precomputed edge vectors / layer
__device__ float g_sums [EMB2];
__device__ float g_sumsq[EMB2];
__device__ float g_scale[EMB2];
__device__ float g_shift[EMB2];

static inline int cdiv(int a, int b) { return (a + b - 1) / b; }

// ---------------- precompute: pad W1, build edge tables ----------------
__global__ void pad_w1_kernel(const float* __restrict__ W1, float* __restrict__ W1p)
{
    int idx = blockIdx.x * blockDim.x + threadIdx.x;
    const int total = NLAY * EMB2 * EMB_P;
    if (idx >= total) return;
    int l   = idx / (EMB2 * EMB_P);
    int rem = idx % (EMB2 * EMB_P);
    int j   = rem / EMB_P;
    int k   = rem % EMB_P;
    W1p[idx] = (k < EMBD) ? W1[(size_t)l * EMB2 * EMBD + (size_t)j * EMBD + k] : 0.f;
}

// etab[l][a0*3+a1][c] = W_bond[l][c][a0] + W_bond[l][c][6+a1]
__global__ void etab_kernel(const float* __restrict__ Wb, float* __restrict__ etab)
{
    int idx = blockIdx.x * blockDim.x + threadIdx.x;
    const int total = NLAY * 9 * EMBD;
    if (idx >= total) return;
    int l    = idx / (9 * EMBD);
    int rem  = idx % (9 * EMBD);
    int comb = rem / EMBD;
    int c    = rem % EMBD;
    int a0 = comb / 3, a1 = comb % 3;
    const float* wb = Wb + (size_t)l * EMBD * 9 + (size_t)c * 9;
    etab[idx] = wb[a0] + wb[6 + a1];
}

// ---------------- z init: z[:, :300] = (1+eps_l)*h ; pad cols = 0 ----------------
__global__ __launch_bounds__(256)
void init_z_kernel(const float* __restrict__ h, const float* __restrict__ eps_l,
                   float* __restrict__ z, int nrows)
{
    long idx = (long)blockIdx.x * blockDim.x + threadIdx.x;
    long total = (long)nrows * (EMB_P / 4);          // 76 float4 per row
    if (idx >= total) return;
    int row = (int)(idx / (EMB_P / 4));
    int c4  = (int)(idx % (EMB_P / 4));
    float4 v = make_float4(0.f, 0.f, 0.f, 0.f);
    if (c4 < EMBD / 4) {
        float s = 1.f + *eps_l;
        float4 hv = *(const float4*)(h + (size_t)row * EMBD + c4 * 4);
        v.x = hv.x * s; v.y = hv.y * s; v.z = hv.z * s; v.w = hv.w * s;
    }
    *(float4*)(z + (size_t)row * EMB_P + c4 * 4) = v;
}

// ---------------- edge gather + relu + scatter-add (one warp per edge) ----------------
__global__ __launch_bounds__(256)
void edge_kernel(const float* __restrict__ h, const float* __restrict__ etab_l,
                 const int* __restrict__ src, const int* __restrict__ dst,
                 const int* __restrict__ ea, float* __restrict__ z, int E)
{
    int warp = (int)(((long)blockIdx.x * blockDim.x + threadIdx.x) >> 5);
    int lane = threadIdx.x & 31;
    if (warp >= E) return;
    int s  = src[warp];
    int d  = dst[warp];
    int a0 = ea[2 * warp];
    int a1 = ea[2 * warp + 1];
    const float* e  = etab_l + (size_t)(a0 * 3 + a1) * EMBD;
    const float* hs = h + (size_t)s * EMBD;
    float* zd = z + (size_t)d * EMB_P;
    for (int c4 = lane; c4 < EMBD / 4; c4 += 32) {
        int c = c4 * 4;
        float4 hv = *(const float4*)(hs + c);
        float4 ev = *(const float4*)(e + c);
        atomicAdd(zd + c    , fmaxf(hv.x + ev.x, 0.f));
        atomicAdd(zd + c + 1, fmaxf(hv.y + ev.y, 0.f));
        atomicAdd(zd + c + 2, fmaxf(hv.z + ev.z, 0.f));
        atomicAdd(zd + c + 3, fmaxf(hv.w + ev.w, 0.f));
    }
}

// ---------------- SGEMM: C[M,Ncols] = A[M,K] * B[Ncols,K]^T + bias ----------------
// 128x128 tile, BK=8, 8x8 per thread, 256 threads. K must be a multiple of 8.
__global__ __launch_bounds__(256)
void sgemm_bias(const float* __restrict__ A, int lda,
                const float* __restrict__ B, int ldb,
                const float* __restrict__ bias,
                float* __restrict__ C, int ldc,
                int M, int Ncols, int K)
{
    __shared__ float As[8][132];
    __shared__ float Bs[8][132];
    const int tid  = threadIdx.x;
    const int brow = blockIdx.y * 128;
    const int bcol = blockIdx.x * 128;
    const int ldRow = tid >> 1;
    const int ldCol = (tid & 1) * 4;
    const int tx = tid & 15;
    const int ty = tid >> 4;

    float acc[8][8];
#pragma unroll
    for (int i = 0; i < 8; i++)
#pragma unroll
        for (int j = 0; j < 8; j++) acc[i][j] = 0.f;

    const int ga = brow + ldRow;
    const int gb = bcol + ldRow;
    const bool aok = ga < M;
    const bool bok = gb < Ncols;
    const float* Aptr = A + (size_t)(aok ? ga : 0) * lda + ldCol;
    const float* Bptr = B + (size_t)(bok ? gb : 0) * ldb + ldCol;

    for (int k0 = 0; k0 < K; k0 += 8) {
        float4 av = make_float4(0.f, 0.f, 0.f, 0.f);
        float4 bv = make_float4(0.f, 0.f, 0.f, 0.f);
        if (aok) av = *(const float4*)(Aptr + k0);
        if (bok) bv = *(const float4*)(Bptr + k0);
        As[ldCol + 0][ldRow] = av.x; As[ldCol + 1][ldRow] = av.y;
        As[ldCol + 2][ldRow] = av.z; As[ldCol + 3][ldRow] = av.w;
        Bs[ldCol + 0][ldRow] = bv.x; Bs[ldCol + 1][ldRow] = bv.y;
        Bs[ldCol + 2][ldRow] = bv.z; Bs[ldCol + 3][ldRow] = bv.w;
        __syncthreads();
#pragma unroll
        for (int k = 0; k < 8; k++) {
            float4 a0 = *(const float4*)&As[k][ty * 8];
            float4 a1 = *(const float4*)&As[k][ty * 8 + 4];
            float4 b0 = *(const float4*)&Bs[k][tx * 8];
            float4 b1 = *(const float4*)&Bs[k][tx * 8 + 4];
            float ra[8] = {a0.x, a0.y, a0.z, a0.w, a1.x, a1.y, a1.z, a1.w};
            float rb[8] = {b0.x, b0.y, b0.z, b0.w, b1.x, b1.y, b1.z, b1.w};
#pragma unroll
            for (int i = 0; i < 8; i++)
#pragma unroll
                for (int j = 0; j < 8; j++)
                    acc[i][j] = fmaf(ra[i], rb[j], acc[i][j]);
        }
        __syncthreads();
    }

#pragma unroll
    for (int i = 0; i < 8; i++) {
        int r = brow + ty * 8 + i;
        if (r >= M) continue;
#pragma unroll
        for (int j = 0; j < 8; j += 4) {
            int c = bcol + tx * 8 + j;
            if (c + 3 < Ncols) {     // Ncols is a multiple of 4
                float4 o;
                o.x = acc[i][j + 0] + bias[c + 0];
                o.y = acc[i][j + 1] + bias[c + 1];
                o.z = acc[i][j + 2] + bias[c + 2];
                o.w = acc[i][j + 3] + bias[c + 3];
                *(float4*)(C + (size_t)r * ldc + c) = o;
            }
        }
    }
}

// ---------------- BN column statistics ----------------
__global__ void zero_stats_kernel(float* __restrict__ sums, float* __restrict__ sumsq, int ncols)
{
    int i = blockIdx.x * blockDim.x + threadIdx.x;
    if (i < ncols) { sums[i] = 0.f; sumsq[i] = 0.f; }
}

__global__ __launch_bounds__(256)
void col_stats_kernel(const float* __restrict__ p, int stride, int ncols, int nrows,
                      float* __restrict__ sums, float* __restrict__ sumsq)
{
    int r0 = blockIdx.x * 256;
    int r1 = min(nrows, r0 + 256);
    float s[3] = {0.f, 0.f, 0.f};
    float q[3] = {0.f, 0.f, 0.f};
    for (int r = r0; r < r1; r++) {
        const float* row = p + (size_t)r * stride;
#pragma unroll
        for (int j = 0; j < 3; j++) {
            int c = threadIdx.x + j * 256;
            if (c < ncols) { float v = row[c]; s[j] += v; q[j] += v * v; }
        }
    }
#pragma unroll
    for (int j = 0; j < 3; j++) {
        int c = threadIdx.x + j * 256;
        if (c < ncols) { atomicAdd(&sums[c], s[j]); atomicAdd(&sumsq[c], q[j]); }
    }
}

__global__ void bn_finalize_kernel(const float* __restrict__ sums, const float* __restrict__ sumsq,
                                   const float* __restrict__ gamma, const float* __restrict__ beta,
                                   int ncols, float invN,
                                   float* __restrict__ scale, float* __restrict__ shift)
{
    int c = blockIdx.x * blockDim.x + threadIdx.x;
    if (c >= ncols) return;
    float m   = sums[c] * invN;
    float var = sumsq[c] * invN - m * m;
    float sc  = gamma[c] * rsqrtf(var + 1e-5f);
    scale[c] = sc;
    shift[c] = beta[c] - m * sc;
}

// ---------------- elementwise BN apply ----------------
__global__ __launch_bounds__(256)
void bnrelu600_kernel(float* __restrict__ t, const float* __restrict__ scale,
                      const float* __restrict__ shift, int nrows)
{
    long idx = (long)blockIdx.x * blockDim.x + threadIdx.x;
    long total = (long)nrows * (EMB2 / 4);
    if (idx >= total) return;
    int row = (int)(idx / (EMB2 / 4));
    int c   = (int)(idx % (EMB2 / 4)) * 4;
    float* p = t + (size_t)row * EMB2 + c;
    float4 v = *(float4*)p;
    v.x = fmaxf(fmaf(v.x, scale[c + 0], shift[c + 0]), 0.f);
    v.y = fmaxf(fmaf(v.y, scale[c + 1], shift[c + 1]), 0.f);
    v.z = fmaxf(fmaf(v.z, scale[c + 2], shift[c + 2]), 0.f);
    v.w = fmaxf(fmaf(v.w, scale[c + 3], shift[c + 3]), 0.f);
    *(float4*)p = v;
}

__global__ __launch_bounds__(256)
void applybn300_kernel(const float* __restrict__ z2, const float* __restrict__ scale,
                       const float* __restrict__ shift, float* __restrict__ out,
                       int nrows, int dorelu)
{
    long idx = (long)blockIdx.x * blockDim.x + threadIdx.x;
    long total = (long)nrows * (EMBD / 4);
    if (idx >= total) return;
    int row = (int)(idx / (EMBD / 4));
    int c   = (int)(idx % (EMBD / 4)) * 4;
    float4 v = *(const float4*)(z2 + (size_t)row * EMBD + c);
    float4 o;
    o.x = fmaf(v.x, scale[c + 0], shift[c + 0]);
    o.y = fmaf(v.y, scale[c + 1], shift[c + 1]);
    o.z = fmaf(v.z, scale[c + 2], shift[c + 2]);
    o.w = fmaf(v.w, scale[c + 3], shift[c + 3]);
    if (dorelu) {
        o.x = fmaxf(o.x, 0.f); o.y = fmaxf(o.y, 0.f);
        o.z = fmaxf(o.z, 0.f); o.w = fmaxf(o.w, 0.f);
    }
    *(float4*)(out + (size_t)row * EMBD + c) = o;
}

// ---------------- launch ----------------
extern "C" void kernel_launch(void* const* d_in, const int* in_sizes, int n_in,
                              void* d_out, int out_size)
{
    const float* x      = (const float*)d_in[0];
    const float* W_bond = (const float*)d_in[1];
    const float* eps    = (const float*)d_in[2];
    const float* W1     = (const float*)d_in[3];
    const float* b1     = (const float*)d_in[4];
    const float* bn1_g  = (const float*)d_in[5];
    const float* bn1_b  = (const float*)d_in[6];
    const float* W2     = (const float*)d_in[7];
    const float* b2     = (const float*)d_in[8];
    const float* bn_g   = (const float*)d_in[9];
    const float* bn_b   = (const float*)d_in[10];
    const int*   eidx   = (const int*)d_in[11];
    const int*   eattr  = (const int*)d_in[12];

    const int nN = in_sizes[0] / EMBD;
    const int nE = in_sizes[11] / 2;
    const int* src = eidx;
    const int* dst = eidx + nE;

    float *h_buf, *z_buf, *t1_buf, *z2_buf, *w1p, *etab, *sums, *sumsq, *scale, *shift;
    cudaGetSymbolAddress((void**)&h_buf,  g_h);
    cudaGetSymbolAddress((void**)&z_buf,  g_z);
    cudaGetSymbolAddress((void**)&t1_buf, g_t1);
    cudaGetSymbolAddress((void**)&z2_buf, g_z2);
    cudaGetSymbolAddress((void**)&w1p,    g_W1p);
    cudaGetSymbolAddress((void**)&etab,   g_etab);
    cudaGetSymbolAddress((void**)&sums,   g_sums);
    cudaGetSymbolAddress((void**)&sumsq,  g_sumsq);
    cudaGetSymbolAddress((void**)&scale,  g_scale);
    cudaGetSymbolAddress((void**)&shift,  g_shift);

    const float invN = 1.0f / (float)nN;

    // precompute padded W1 and edge tables
    pad_w1_kernel<<<cdiv(NLAY * EMB2 * EMB_P, 256), 256>>>(W1, w1p);
    etab_kernel  <<<cdiv(NLAY * 9 * EMBD, 256), 256>>>(W_bond, etab);

    for (int l = 0; l < NLAY; l++) {
        const float* h_in = (l == 0) ? x : h_buf;

        // z = (1+eps)*h (padded), then scatter-add relu(h[src]+e) into z[dst]
        init_z_kernel<<<cdiv(nN * (EMB_P / 4), 256), 256>>>(h_in, eps + l, z_buf, nN);
        edge_kernel<<<cdiv(nE * 32, 256), 256>>>(h_in, etab + (size_t)l * 9 * EMBD,
                                                 src, dst, eattr, z_buf, nE);

        // t1 = z @ W1^T + b1   [nN, 600], K=304 (padded)
        {
            dim3 grid(cdiv(EMB2, 128), cdiv(nN, 128));
            sgemm_bias<<<grid, 256>>>(z_buf, EMB_P,
                                      w1p + (size_t)l * EMB2 * EMB_P, EMB_P,
                                      b1 + (size_t)l * EMB2,
                                      t1_buf, EMB2, nN, EMB2, EMB_P);
        }

        // BN1 stats + relu(bn) in-place
        zero_stats_kernel<<<cdiv(EMB2, 256), 256>>>(sums, sumsq, EMB2);
        col_stats_kernel<<<cdiv(nN, 256), 256>>>(t1_buf, EMB2, EMB2, nN, sums, sumsq);
        bn_finalize_kernel<<<cdiv(EMB2, 256), 256>>>(sums, sumsq,
                                                     bn1_g + (size_t)l * EMB2,
                                                     bn1_b + (size_t)l * EMB2,
                                                     EMB2, invN, scale, shift);
        bnrelu600_kernel<<<cdiv(nN * (EMB2 / 4), 256), 256>>>(t1_buf, scale, shift, nN);

        // z2 = t1 @ W2^T + b2   [nN, 300], K=600
        {
            dim3 grid(cdiv(EMBD, 128), cdiv(nN, 128));
            sgemm_bias<<<grid, 256>>>(t1_buf, EMB2,
                                      W2 + (size_t)l * EMBD * EMB2, EMB2,
                                      b2 + (size_t)l * EMBD,
                                      z2_buf, EMBD, nN, EMBD, EMB2);
        }

        // BN2 stats + apply (+relu except last layer); final layer writes d_out
        zero_stats_kernel<<<cdiv(EMBD, 256), 256>>>(sums, sumsq, EMBD);
        col_stats_kernel<<<cdiv(nN, 256), 256>>>(z2_buf, EMBD, EMBD, nN, sums, sumsq);
        bn_finalize_kernel<<<cdiv(EMBD, 256), 256>>>(sums, sumsq,
                                                     bn_g + (size_t)l * EMBD,
                                                     bn_b + (size_t)l * EMBD,
                                                     EMBD, invN, scale, shift);
        float* h_out = (l == NLAY - 1) ? (float*)d_out : h_buf;
        applybn300_kernel<<<cdiv(nN * (EMBD / 4), 256), 256>>>(z2_buf, scale, shift,
                                                               h_out, nN, (l < NLAY - 1) ? 1 : 0);
    }
}

// round 9
// speedup vs baseline: 1.6618x; 1.6618x over previous
#include <cuda_runtime.h>
#include <cuda_bf16.h>
#include <cstdint>

#define EMBD   300
#define EMB_P  320      // z stride, K-pad for gemm1 (10 chunks of 32)
#define EMB2   600
#define EMB2_P 640      // t1 stride, K-pad for gemm2 (20 chunks of 32)
#define NLAY   5
#define NMAX   100000

#define NT1 5           // gemm1 N tiles (640 cols)
#define KC1 10          // gemm1 K chunks of 32
#define NT2 3           // gemm2 N tiles (384 cols)
#define KC2 20          // gemm2 K chunks of 32
#define KCH 32
#define TILE_ELEMS 4096 // 128 rows x 32 cols bf16
#define APAD 40         // padded smem row length (bf16 elems)
#define AT_BYTES (128*APAD*2)       // 10240
#define STAGE_B (4*AT_BYTES)        // 40960: Ah, Al, Bh, Bl
#define SMEM_DYN (2*STAGE_B)        // 81920

#define W1T_ELEMS (NT1*KC1*TILE_ELEMS)   // 204800
#define W2T_ELEMS (NT2*KC2*TILE_ELEMS)   // 245760

// ---------------- static scratch ----------------
__device__ float g_h  [(size_t)NMAX * EMBD];
__device__ float g_z  [(size_t)NMAX * EMB_P];
__device__ float g_t1 [(size_t)NMAX * EMB2_P];
__device__ float g_z2 [(size_t)NMAX * EMBD];
__device__ float g_etab[NLAY * 9 * EMBD];
__device__ float g_sums [EMB2];
__device__ float g_sumsq[EMB2];
__device__ float g_scale[EMB2];
__device__ float g_shift[EMB2];
// 16B-aligned weight tile storage (uint4 so cp.async/float4 access is legal)
__device__ uint4 g_w1h[NLAY * W1T_ELEMS / 8];
__device__ uint4 g_w1l[NLAY * W1T_ELEMS / 8];
__device__ uint4 g_w2h[NLAY * W2T_ELEMS / 8];
__device__ uint4 g_w2l[NLAY * W2T_ELEMS / 8];

static inline int cdiv(int a, int b) { return (a + b - 1) / b; }

// ---------------- PTX helpers (all baseline-arch features) ----------------
__device__ __forceinline__ uint32_t smem_u32(const void* p) {
    uint32_t a;
    asm("{ .reg .u64 t; cvta.to.shared.u64 t, %1; cvt.u32.u64 %0, t; }" : "=r"(a) : "l"(p));
    return a;
}
__device__ __forceinline__ void ldsm4(uint32_t* r, uint32_t addr) {
    asm volatile("ldmatrix.sync.aligned.m8n8.x4.shared.b16 {%0,%1,%2,%3}, [%4];"
                 : "=r"(r[0]), "=r"(r[1]), "=r"(r[2]), "=r"(r[3]) : "r"(addr));
}
__device__ __forceinline__ void mma_bf16(float* d, const uint32_t* a, const uint32_t* b) {
    asm volatile("mma.sync.aligned.m16n8k16.row.col.f32.bf16.bf16.f32 "
                 "{%0,%1,%2,%3}, {%4,%5,%6,%7}, {%8,%9}, {%0,%1,%2,%3};"
                 : "+f"(d[0]), "+f"(d[1]), "+f"(d[2]), "+f"(d[3])
                 : "r"(a[0]), "r"(a[1]), "r"(a[2]), "r"(a[3]), "r"(b[0]), "r"(b[1]));
}
#define CPA16(dst, src) asm volatile("cp.async.cg.shared.global [%0], [%1], 16;" :: "r"(dst), "l"(src) : "memory")
#define CPA_COMMIT()    asm volatile("cp.async.commit_group;" ::: "memory")
#define CPA_WAIT0()     asm volatile("cp.async.wait_group 0;" ::: "memory")

__device__ __forceinline__ void split2(float a, float b, uint32_t& hi, uint32_t& lo) {
    __nv_bfloat16 ha = __float2bfloat16(a), hb = __float2bfloat16(b);
    float ra = a - __bfloat162float(ha), rb = b - __bfloat162float(hb);
    __nv_bfloat16 la = __float2bfloat16(ra), lb = __float2bfloat16(rb);
    hi = ((uint32_t)__bfloat16_as_ushort(hb) << 16) | (uint32_t)__bfloat16_as_ushort(ha);
    lo = ((uint32_t)__bfloat16_as_ushort(lb) << 16) | (uint32_t)__bfloat16_as_ushort(la);
}

// ---------------- weight tile prep: [l][ntile][kchunk][128 N][32 K] bf16, hi/lo ----------------
__global__ void prep_w_tiles(const float* __restrict__ W, int Nw, int Kw,
                             int ntiles, int nkch,
                             __nv_bfloat16* __restrict__ Th, __nv_bfloat16* __restrict__ Tl)
{
    long idx = (long)blockIdx.x * blockDim.x + threadIdx.x;
    long per_layer = (long)ntiles * nkch * TILE_ELEMS;
    long total = (long)NLAY * per_layer;
    if (idx >= total) return;
    int  l    = (int)(idx / per_layer);
    long rem  = idx % per_layer;
    int  t    = (int)(rem / ((long)nkch * TILE_ELEMS));
    int  rem2 = (int)(rem % ((long)nkch * TILE_ELEMS));
    int  kc   = rem2 >> 12;
    int  e    = rem2 & (TILE_ELEMS - 1);
    int  row  = e >> 5, col = e & 31;
    int  grow = t * 128 + row, gk = kc * KCH + col;
    float v = (grow < Nw && gk < Kw) ? W[(size_t)l * Nw * Kw + (size_t)grow * Kw + gk] : 0.f;
    __nv_bfloat16 h  = __float2bfloat16(v);
    __nv_bfloat16 lo = __float2bfloat16(v - __bfloat162float(h));
    Th[idx] = h; Tl[idx] = lo;
}

// etab[l][a0*3+a1][c] = W_bond[l][c][a0] + W_bond[l][c][6+a1]
__global__ void etab_kernel(const float* __restrict__ Wb, float* __restrict__ etab)
{
    int idx = blockIdx.x * blockDim.x + threadIdx.x;
    const int total = NLAY * 9 * EMBD;
    if (idx >= total) return;
    int l = idx / (9 * EMBD);
    int rem = idx % (9 * EMBD);
    int comb = rem / EMBD;
    int c = rem % EMBD;
    int a0 = comb / 3, a1 = comb % 3;
    const float* wb = Wb + (size_t)l * EMBD * 9 + (size_t)c * 9;
    etab[idx] = wb[a0] + wb[6 + a1];
}

// ---------------- z init: z[:, :300] = (1+eps)*h ; pad cols 0 ----------------
__global__ __launch_bounds__(256)
void init_z_kernel(const float* __restrict__ h, const float* __restrict__ eps_l,
                   float* __restrict__ z, int nrows)
{
    long idx = (long)blockIdx.x * blockDim.x + threadIdx.x;
    long total = (long)nrows * (EMB_P / 4);
    if (idx >= total) return;
    int row = (int)(idx / (EMB_P / 4));
    int c4  = (int)(idx % (EMB_P / 4));
    float4 v = make_float4(0.f, 0.f, 0.f, 0.f);
    if (c4 < EMBD / 4) {
        float s = 1.f + *eps_l;
        float4 hv = *(const float4*)(h + (size_t)row * EMBD + c4 * 4);
        v.x = hv.x * s; v.y = hv.y * s; v.z = hv.z * s; v.w = hv.w * s;
    }
    *(float4*)(z + (size_t)row * EMB_P + c4 * 4) = v;
}

// ---------------- edge gather + relu + scatter-add ----------------
__global__ __launch_bounds__(256)
void edge_kernel(const float* __restrict__ h, const float* __restrict__ etab_l,
                 const int* __restrict__ src, const int* __restrict__ dst,
                 const int* __restrict__ ea, float* __restrict__ z, int E)
{
    int warp = (int)(((long)blockIdx.x * blockDim.x + threadIdx.x) >> 5);
    int lane = threadIdx.x & 31;
    if (warp >= E) return;
    int s  = src[warp];
    int d  = dst[warp];
    int a0 = ea[2 * warp];
    int a1 = ea[2 * warp + 1];
    const float* e  = etab_l + (size_t)(a0 * 3 + a1) * EMBD;
    const float* hs = h + (size_t)s * EMBD;
    float* zd = z + (size_t)d * EMB_P;
    for (int c4 = lane; c4 < EMBD / 4; c4 += 32) {
        int c = c4 * 4;
        float4 hv = *(const float4*)(hs + c);
        float4 ev = *(const float4*)(e + c);
        atomicAdd(zd + c    , fmaxf(hv.x + ev.x, 0.f));
        atomicAdd(zd + c + 1, fmaxf(hv.y + ev.y, 0.f));
        atomicAdd(zd + c + 2, fmaxf(hv.z + ev.z, 0.f));
        atomicAdd(zd + c + 3, fmaxf(hv.w + ev.w, 0.f));
    }
}

// ---------------- bf16-split GEMM via mma.sync (HMMA) ----------------
// C[M,*] = A[M,K](fp32) @ B^T + bias. B pre-split bf16 tiles [ntile][kch][128][32].
// CTA 128x128, 8 warps each 64x32, K-chunk 32, double-buffered smem.
__global__ __launch_bounds__(256)
void mma_gemm(const float* __restrict__ A, int lda,
              const uint4* __restrict__ Bh, const uint4* __restrict__ Bl,
              const float* __restrict__ bias, int nbias,
              float* __restrict__ C, int ldc, int nstore,
              int M, int nkch)
{
    extern __shared__ char smem_raw[];
    const uint32_t sb = smem_u32(smem_raw);

    const int tid  = threadIdx.x;
    const int wid  = tid >> 5;
    const int lane = tid & 31;
    const int brow = blockIdx.y * 128;
    const int bcol = blockIdx.x * 128;

    // warp tile: 64(M) x 32(N)
    const int mbase = (wid & 1) * 64;
    const int nbase = (wid >> 1) * 32;

    // ldmatrix lane addressing
    const int q = lane >> 3;
    const int lrowA = (lane & 7) + (q & 1) * 8;        // A: row within 16
    const int lcolA = (q >> 1) * 8;                    // A: k offset 0/8
    const int lrowB = (lane & 7) + (q >> 1) * 8;       // B: n within 16
    const int lcolB = (q & 1) * 8;                     // B: k offset 0/8

    // A global load mapping: 2 threads/row, 16 cols each
    const int arow = tid >> 1;
    const int acb  = (tid & 1) * 16;
    const int grow = brow + arow;
    const bool aok = grow < M;
    const float* aptr = A + (size_t)(aok ? grow : 0) * lda + acb;

    const long btile0 = (long)blockIdx.x * nkch * TILE_ELEMS;   // in bf16 elems

    float acc[4][4][4];
#pragma unroll
    for (int i = 0; i < 4; i++)
#pragma unroll
        for (int j = 0; j < 4; j++)
#pragma unroll
            for (int k = 0; k < 4; k++) acc[i][j][k] = 0.f;

    for (int c = 0; c < nkch; ++c) {
        const int cur = c & 1;
        const uint32_t sAh = sb + cur * STAGE_B;
        const uint32_t sAl = sAh + AT_BYTES;
        const uint32_t sBh = sAh + 2 * AT_BYTES;
        const uint32_t sBl = sAh + 3 * AT_BYTES;

        if (c == 0) {   // synchronous fill of buffer 0
            const float4* ap = (const float4*)(aptr);
#pragma unroll
            for (int j = 0; j < 4; j++) {
                float4 v = aok ? ap[j] : make_float4(0.f, 0.f, 0.f, 0.f);
                uint32_t h01, l01, h23, l23;
                split2(v.x, v.y, h01, l01);
                split2(v.z, v.w, h23, l23);
                uint32_t off = (uint32_t)(arow * APAD + acb + j * 4) * 2;
                asm volatile("st.shared.v2.b32 [%0], {%1,%2};" :: "r"(sAh + off), "r"(h01), "r"(h23) : "memory");
                asm volatile("st.shared.v2.b32 [%0], {%1,%2};" :: "r"(sAl + off), "r"(l01), "r"(l23) : "memory");
            }
            const long cb8 = btile0 / 8;   // uint4 index of tile block start
#pragma unroll
            for (int j = 0; j < 2; j++) {
                int i = tid + j * 256;
                int row = i >> 2, ko = (i & 3) * 8;
                uint32_t soff = (uint32_t)(row * APAD + ko) * 2;
                CPA16(sBh + soff, Bh + cb8 + i);
                CPA16(sBl + soff, Bl + cb8 + i);
            }
            CPA_COMMIT(); CPA_WAIT0();
            __syncthreads();
        }

        // ---- prefetch next chunk ----
        float4 av[4];
        if (c + 1 < nkch) {
            const float4* ap = (const float4*)(aptr + (c + 1) * KCH);
#pragma unroll
            for (int j = 0; j < 4; j++)
                av[j] = aok ? ap[j] : make_float4(0.f, 0.f, 0.f, 0.f);
            const uint32_t nstage = sb + ((c + 1) & 1) * STAGE_B;
            const long cb8 = (btile0 + (long)(c + 1) * TILE_ELEMS) / 8;
#pragma unroll
            for (int j = 0; j < 2; j++) {
                int i = tid + j * 256;
                int row = i >> 2, ko = (i & 3) * 8;
                uint32_t soff = (uint32_t)(row * APAD + ko) * 2;
                CPA16(nstage + 2 * AT_BYTES + soff, Bh + cb8 + i);
                CPA16(nstage + 3 * AT_BYTES + soff, Bl + cb8 + i);
            }
            CPA_COMMIT();
        }

        // ---- compute chunk c: 2 k-steps of 16 ----
#pragma unroll
        for (int ks = 0; ks < 2; ks++) {
            uint32_t fB_h[4][2], fB_l[4][2];
#pragma unroll
            for (int ntp = 0; ntp < 2; ntp++) {
                uint32_t r4[4];
                uint32_t boff = (uint32_t)((nbase + ntp * 16 + lrowB) * APAD + ks * 16 + lcolB) * 2;
                ldsm4(r4, sBh + boff);
                fB_h[ntp * 2][0] = r4[0]; fB_h[ntp * 2][1] = r4[1];
                fB_h[ntp * 2 + 1][0] = r4[2]; fB_h[ntp * 2 + 1][1] = r4[3];
                ldsm4(r4, sBl + boff);
                fB_l[ntp * 2][0] = r4[0]; fB_l[ntp * 2][1] = r4[1];
                fB_l[ntp * 2 + 1][0] = r4[2]; fB_l[ntp * 2 + 1][1] = r4[3];
            }
#pragma unroll
            for (int mt = 0; mt < 4; mt++) {
                uint32_t aoff = (uint32_t)((mbase + mt * 16 + lrowA) * APAD + ks * 16 + lcolA) * 2;
                uint32_t fA[4];
                ldsm4(fA, sAh + aoff);     // hi
#pragma unroll
                for (int nt = 0; nt < 4; nt++) {
                    mma_bf16(acc[mt][nt], fA, fB_h[nt]);
                    mma_bf16(acc[mt][nt], fA, fB_l[nt]);
                }
                ldsm4(fA, sAl + aoff);     // lo
#pragma unroll
                for (int nt = 0; nt < 4; nt++)
                    mma_bf16(acc[mt][nt], fA, fB_h[nt]);
            }
        }

        // ---- store prefetched A, drain cp.async ----
        if (c + 1 < nkch) {
            const uint32_t nstage = sb + ((c + 1) & 1) * STAGE_B;
#pragma unroll
            for (int j = 0; j < 4; j++) {
                uint32_t h01, l01, h23, l23;
                split2(av[j].x, av[j].y, h01, l01);
                split2(av[j].z, av[j].w, h23, l23);
                uint32_t off = (uint32_t)(arow * APAD + acb + j * 4) * 2;
                asm volatile("st.shared.v2.b32 [%0], {%1,%2};" :: "r"(nstage + off), "r"(h01), "r"(h23) : "memory");
                asm volatile("st.shared.v2.b32 [%0], {%1,%2};" :: "r"(nstage + AT_BYTES + off), "r"(l01), "r"(l23) : "memory");
            }
            CPA_WAIT0();
        }
        __syncthreads();
    }

    // ---- epilogue: acc + bias -> C ----
    const int gtr = lane >> 2;        // row group 0..7
    const int gtc = (lane & 3) * 2;   // col pair
#pragma unroll
    for (int mt = 0; mt < 4; mt++) {
        int r0 = brow + mbase + mt * 16 + gtr;
        int r1 = r0 + 8;
#pragma unroll
        for (int nt = 0; nt < 4; nt++) {
            int col = bcol + nbase + nt * 8 + gtc;
            if (col < nstore) {
                float b0 = (col     < nbias) ? bias[col]     : 0.f;
                float b1 = (col + 1 < nbias) ? bias[col + 1] : 0.f;
                if (r0 < M) {
                    float2 o = make_float2(acc[mt][nt][0] + b0, acc[mt][nt][1] + b1);
                    *(float2*)(C + (size_t)r0 * ldc + col) = o;
                }
                if (r1 < M) {
                    float2 o = make_float2(acc[mt][nt][2] + b0, acc[mt][nt][3] + b1);
                    *(float2*)(C + (size_t)r1 * ldc + col) = o;
                }
            }
        }
    }
}

// ---------------- BN ----------------
__global__ void zero_stats_kernel(float* __restrict__ sums, float* __restrict__ sumsq, int ncols)
{
    int i = blockIdx.x * blockDim.x + threadIdx.x;
    if (i < ncols) { sums[i] = 0.f; sumsq[i] = 0.f; }
}

__global__ __launch_bounds__(256)
void col_stats_kernel(const float* __restrict__ p, int stride, int ncols, int nrows,
                      float* __restrict__ sums, float* __restrict__ sumsq)
{
    int r0 = blockIdx.x * 256;
    int r1 = min(nrows, r0 + 256);
    float s[3] = {0.f, 0.f, 0.f};
    float q[3] = {0.f, 0.f, 0.f};
    for (int r = r0; r < r1; r++) {
        const float* row = p + (size_t)r * stride;
#pragma unroll
        for (int j = 0; j < 3; j++) {
            int c = threadIdx.x + j * 256;
            if (c < ncols) { float v = row[c]; s[j] += v; q[j] += v * v; }
        }
    }
#pragma unroll
    for (int j = 0; j < 3; j++) {
        int c = threadIdx.x + j * 256;
        if (c < ncols) { atomicAdd(&sums[c], s[j]); atomicAdd(&sumsq[c], q[j]); }
    }
}

__global__ void bn_finalize_kernel(const float* __restrict__ sums, const float* __restrict__ sumsq,
                                   const float* __restrict__ gamma, const float* __restrict__ beta,
                                   int ncols, float invN,
                                   float* __restrict__ scale, float* __restrict__ shift)
{
    int c = blockIdx.x * blockDim.x + threadIdx.x;
    if (c >= ncols) return;
    float m   = sums[c] * invN;
    float var = sumsq[c] * invN - m * m;
    float sc  = gamma[c] * rsqrtf(var + 1e-5f);
    scale[c] = sc;
    shift[c] = beta[c] - m * sc;
}

__global__ __launch_bounds__(256)
void bnrelu600_kernel(float* __restrict__ t, const float* __restrict__ scale,
                      const float* __restrict__ shift, int nrows)
{
    long idx = (long)blockIdx.x * blockDim.x + threadIdx.x;
    long total = (long)nrows * (EMB2 / 4);
    if (idx >= total) return;
    int row = (int)(idx / (EMB2 / 4));
    int c   = (int)(idx % (EMB2 / 4)) * 4;
    float* p = t + (size_t)row * EMB2_P + c;
    float4 v = *(float4*)p;
    v.x = fmaxf(fmaf(v.x, scale[c + 0], shift[c + 0]), 0.f);
    v.y = fmaxf(fmaf(v.y, scale[c + 1], shift[c + 1]), 0.f);
    v.z = fmaxf(fmaf(v.z, scale[c + 2], shift[c + 2]), 0.f);
    v.w = fmaxf(fmaf(v.w, scale[c + 3], shift[c + 3]), 0.f);
    *(float4*)p = v;
}

__global__ __launch_bounds__(256)
void applybn300_kernel(const float* __restrict__ z2, const float* __restrict__ scale,
                       const float* __restrict__ shift, float* __restrict__ out,
                       int nrows, int dorelu)
{
    long idx = (long)blockIdx.x * blockDim.x + threadIdx.x;
    long total = (long)nrows * (EMBD / 4);
    if (idx >= total) return;
    int row = (int)(idx / (EMBD / 4));
    int c   = (int)(idx % (EMBD / 4)) * 4;
    float4 v = *(const float4*)(z2 + (size_t)row * EMBD + c);
    float4 o;
    o.x = fmaf(v.x, scale[c + 0], shift[c + 0]);
    o.y = fmaf(v.y, scale[c + 1], shift[c + 1]);
    o.z = fmaf(v.z, scale[c + 2], shift[c + 2]);
    o.w = fmaf(v.w, scale[c + 3], shift[c + 3]);
    if (dorelu) {
        o.x = fmaxf(o.x, 0.f); o.y = fmaxf(o.y, 0.f);
        o.z = fmaxf(o.z, 0.f); o.w = fmaxf(o.w, 0.f);
    }
    *(float4*)(out + (size_t)row * EMBD + c) = o;
}

// ---------------- launch ----------------
extern "C" void kernel_launch(void* const* d_in, const int* in_sizes, int n_in,
                              void* d_out, int out_size)
{
    const float* x      = (const float*)d_in[0];
    const float* W_bond = (const float*)d_in[1];
    const float* eps    = (const float*)d_in[2];
    const float* W1     = (const float*)d_in[3];
    const float* b1     = (const float*)d_in[4];
    const float* bn1_g  = (const float*)d_in[5];
    const float* bn1_b  = (const float*)d_in[6];
    const float* W2     = (const float*)d_in[7];
    const float* b2     = (const float*)d_in[8];
    const float* bn_g   = (const float*)d_in[9];
    const float* bn_b   = (const float*)d_in[10];
    const int*   eidx   = (const int*)d_in[11];
    const int*   eattr  = (const int*)d_in[12];

    const int nN = in_sizes[0] / EMBD;
    const int nE = in_sizes[11] / 2;
    const int* src = eidx;
    const int* dst = eidx + nE;

    float *h_buf, *z_buf, *t1_buf, *z2_buf, *etab, *sums, *sumsq, *scale, *shift;
    uint4 *w1h, *w1l, *w2h, *w2l;
    cudaGetSymbolAddress((void**)&h_buf,  g_h);
    cudaGetSymbolAddress((void**)&z_buf,  g_z);
    cudaGetSymbolAddress((void**)&t1_buf, g_t1);
    cudaGetSymbolAddress((void**)&z2_buf, g_z2);
    cudaGetSymbolAddress((void**)&etab,   g_etab);
    cudaGetSymbolAddress((void**)&sums,   g_sums);
    cudaGetSymbolAddress((void**)&sumsq,  g_sumsq);
    cudaGetSymbolAddress((void**)&scale,  g_scale);
    cudaGetSymbolAddress((void**)&shift,  g_shift);
    cudaGetSymbolAddress((void**)&w1h, g_w1h);
    cudaGetSymbolAddress((void**)&w1l, g_w1l);
    cudaGetSymbolAddress((void**)&w2h, g_w2h);
    cudaGetSymbolAddress((void**)&w2l, g_w2l);

    cudaFuncSetAttribute(mma_gemm, cudaFuncAttributeMaxDynamicSharedMemorySize, SMEM_DYN);

    const float invN = 1.0f / (float)nN;
    const int ntm = cdiv(nN, 128);

    etab_kernel<<<cdiv(NLAY * 9 * EMBD, 256), 256>>>(W_bond, etab);
    prep_w_tiles<<<cdiv(NLAY * W1T_ELEMS, 256), 256>>>(W1, EMB2, EMBD, NT1, KC1,
                                                       (__nv_bfloat16*)w1h, (__nv_bfloat16*)w1l);
    prep_w_tiles<<<cdiv(NLAY * W2T_ELEMS, 256), 256>>>(W2, EMBD, EMB2, NT2, KC2,
                                                       (__nv_bfloat16*)w2h, (__nv_bfloat16*)w2l);

    for (int l = 0; l < NLAY; l++) {
        const float* h_in = (l == 0) ? x : h_buf;

        init_z_kernel<<<cdiv(nN * (EMB_P / 4), 256), 256>>>(h_in, eps + l, z_buf, nN);
        edge_kernel<<<cdiv(nE * 32, 256), 256>>>(h_in, etab + (size_t)l * 9 * EMBD,
                                                 src, dst, eattr, z_buf, nE);

        // t1 = z @ W1^T + b1   [nN, 600] (stride 640; pad cols exact 0)
        {
            dim3 grid(NT1, ntm);
            mma_gemm<<<grid, 256, SMEM_DYN>>>(z_buf, EMB_P,
                                              w1h + (size_t)l * W1T_ELEMS / 8,
                                              w1l + (size_t)l * W1T_ELEMS / 8,
                                              b1 + (size_t)l * EMB2, EMB2,
                                              t1_buf, EMB2_P, EMB2_P, nN, KC1);
        }

        zero_stats_kernel<<<cdiv(EMB2, 256), 256>>>(sums, sumsq, EMB2);
        col_stats_kernel<<<cdiv(nN, 256), 256>>>(t1_buf, EMB2_P, EMB2, nN, sums, sumsq);
        bn_finalize_kernel<<<cdiv(EMB2, 256), 256>>>(sums, sumsq,
                                                     bn1_g + (size_t)l * EMB2,
                                                     bn1_b + (size_t)l * EMB2,
                                                     EMB2, invN, scale, shift);
        bnrelu600_kernel<<<cdiv(nN * (EMB2 / 4), 256), 256>>>(t1_buf, scale, shift, nN);

        // z2 = t1 @ W2^T + b2   [nN, 300]
        {
            dim3 grid(NT2, ntm);
            mma_gemm<<<grid, 256, SMEM_DYN>>>(t1_buf, EMB2_P,
                                              w2h + (size_t)l * W2T_ELEMS / 8,
                                              w2l + (size_t)l * W2T_ELEMS / 8,
                                              b2 + (size_t)l * EMBD, EMBD,
                                              z2_buf, EMBD, EMBD, nN, KC2);
        }

        zero_stats_kernel<<<cdiv(EMBD, 256), 256>>>(sums, sumsq, EMBD);
        col_stats_kernel<<<cdiv(nN, 256), 256>>>(z2_buf, EMBD, EMBD, nN, sums, sumsq);
        bn_finalize_kernel<<<cdiv(EMBD, 256), 256>>>(sums, sumsq,
                                                     bn_g + (size_t)l * EMBD,
                                                     bn_b + (size_t)l * EMBD,
                                                     EMBD, invN, scale, shift);
        float* h_out = (l == NLAY - 1) ? (float*)d_out : h_buf;
        applybn300_kernel<<<cdiv(nN * (EMBD / 4), 256), 256>>>(z2_buf, scale, shift,
                                                               h_out, nN, (l < NLAY - 1) ? 1 : 0);
    }
}